// round 5
// baseline (speedup 1.0000x reference)
#include <cuda_runtime.h>
#include <cstdint>

// Problem shape
constexpr int Hn = 16, Sq = 2048, Dh = 64;
constexpr float SCALE = 0.125f;

// Tiling: CTA = 256 q-rows, 8 warps x 32 rows; 64-key tiles, double-buffered
constexpr int MQ = 256, NK = 64, THREADS = 256;
constexpr int NITER = Sq / NK;                    // 32

// smem strides (floats / bytes)
constexpr int QSF = 68, KSF = 68, VSF = 72;
constexpr int QROW = QSF * 4, KROW = KSF * 4, VROW = VSF * 4;   // 272/272/288
constexpr int Q_OFF = 0;
constexpr int KBUF  = NK * KROW;                  // 17408
constexpr int K_OFF = Q_OFF + MQ * QROW;          // 69632
constexpr int VBUF  = NK * VROW;                  // 18432
constexpr int V_OFF = K_OFF + 2 * KBUF;           // 104448
constexpr int SMEM_BYTES = V_OFF + 2 * VBUF;      // 141312

__device__ __forceinline__ uint32_t smem_u32(const void* p) {
    uint32_t a;
    asm("{ .reg .u64 t; cvta.to.shared.u64 t, %1; cvt.u32.u64 %0, t; }" : "=r"(a) : "l"(p));
    return a;
}
__device__ __forceinline__ uint32_t f2tf(float f) {
    uint32_t r;
    asm("cvt.rna.tf32.f32 %0, %1;" : "=r"(r) : "f"(f));
    return r;
}
__device__ __forceinline__ void cp16(uint32_t dst, const void* src) {
    asm volatile("cp.async.cg.shared.global [%0], [%1], 16;" :: "r"(dst), "l"(src));
}
__device__ __forceinline__ void mma_tf32(float* c, const uint32_t* a, uint32_t b0, uint32_t b1) {
    asm volatile(
        "mma.sync.aligned.m16n8k8.row.col.f32.tf32.tf32.f32 "
        "{%0,%1,%2,%3}, {%4,%5,%6,%7}, {%8,%9}, {%0,%1,%2,%3};"
        : "+f"(c[0]), "+f"(c[1]), "+f"(c[2]), "+f"(c[3])
        : "r"(a[0]), "r"(a[1]), "r"(a[2]), "r"(a[3]), "r"(b0), "r"(b1));
}

__global__ __launch_bounds__(THREADS)
void sdpa_mma3(const float* __restrict__ Q, const float* __restrict__ K,
               const float* __restrict__ V, const unsigned int* __restrict__ mask,
               float* __restrict__ O)
{
    extern __shared__ char smc[];
    const uint32_t sb = smem_u32(smc);

    const int tid  = threadIdx.x;
    const int lane = tid & 31;
    const int warp = tid >> 5;
    const int g    = lane >> 2;
    const int tg   = lane & 3;

    const int nqb = Sq / MQ;                 // 8
    const int bh  = blockIdx.x / nqb;
    const int qb  = blockIdx.x % nqb;
    const int b   = bh / Hn;

    const float* Kbh = K + (size_t)bh * Sq * Dh;
    const float* Vbh = V + (size_t)bh * Sq * Dh;

    // ---- cp.async prefetch of K/V tile t into buffer bi (V rows pair-permuted) ----
    auto prefetch = [&](int t, int bi) {
        const float* ksrc = Kbh + (size_t)t * NK * Dh;
        const float* vsrc = Vbh + (size_t)t * NK * Dh;
        #pragma unroll
        for (int i = 0; i < 4; ++i) {
            int idx = tid + i * THREADS;     // 0..1023
            int r = idx >> 4, c = idx & 15;
            cp16(sb + K_OFF + bi * KBUF + r * KROW + c * 16, ksrc + r * Dh + c * 4);
            int rp = (r & 0x38) | ((r & 1) << 2) | ((r & 7) >> 1);
            cp16(sb + V_OFF + bi * VBUF + rp * VROW + c * 16, vsrc + r * Dh + c * 4);
        }
    };
    prefetch(0, 0); asm volatile("cp.async.commit_group;");
    prefetch(1, 1); asm volatile("cp.async.commit_group;");

    // ---- stage Q (pre-converted tf32) into smem ----
    {
        const float4* qg = (const float4*)(Q + ((size_t)bh * Sq + (size_t)qb * MQ) * Dh);
        #pragma unroll
        for (int i = 0; i < 16; ++i) {
            int idx = tid + i * THREADS;     // 0..4095
            int r = idx >> 4, c4 = idx & 15;
            float4 v = qg[idx];
            uint4 u = make_uint4(f2tf(v.x), f2tf(v.y), f2tf(v.z), f2tf(v.w));
            *(uint4*)(smc + Q_OFF + r * QROW + c4 * 16) = u;
        }
    }

    // mask row pointers: this thread covers rows qbase + 8*j, j=0..3
    const int qbase = qb * MQ + warp * 32 + g;
    const unsigned int* mr[4];
    #pragma unroll
    for (int j = 0; j < 4; ++j)
        mr[j] = mask + ((size_t)b * Sq + (size_t)(qbase + 8 * j)) * Sq;

    float ow[2][8][4];
    #pragma unroll
    for (int gp = 0; gp < 2; ++gp)
        #pragma unroll
        for (int n = 0; n < 8; ++n)
            ow[gp][n][0] = ow[gp][n][1] = ow[gp][n][2] = ow[gp][n][3] = 0.f;
    float mrw[4] = {-1e30f, -1e30f, -1e30f, -1e30f};
    float lrw[4] = {0.f, 0.f, 0.f, 0.f};

    const uint32_t* Qw = (const uint32_t*)(smc + Q_OFF) + (warp * 32) * QSF;

    for (int t = 0; t < NITER; ++t) {
        const int bi = t & 1;
        asm volatile("cp.async.wait_group 1;" ::: "memory");
        __syncthreads();

        const float* Kb = (const float*)(smc + K_OFF + bi * KBUF);
        const float* Vb = (const float*)(smc + V_OFF + bi * VBUF);

        // ---- QK^T ----
        float sc[2][8][4];
        #pragma unroll
        for (int gp = 0; gp < 2; ++gp)
            #pragma unroll
            for (int n = 0; n < 8; ++n)
                sc[gp][n][0] = sc[gp][n][1] = sc[gp][n][2] = sc[gp][n][3] = 0.f;

        #pragma unroll
        for (int ks = 0; ks < 8; ++ks) {
            const int col = ks * 8 + tg;
            uint32_t a0[4], a1[4];
            a0[0] = Qw[(g     ) * QSF + col];
            a0[1] = Qw[(g +  8) * QSF + col];
            a0[2] = Qw[(g     ) * QSF + col + 4];
            a0[3] = Qw[(g +  8) * QSF + col + 4];
            a1[0] = Qw[(g + 16) * QSF + col];
            a1[1] = Qw[(g + 24) * QSF + col];
            a1[2] = Qw[(g + 16) * QSF + col + 4];
            a1[3] = Qw[(g + 24) * QSF + col + 4];
            #pragma unroll
            for (int n = 0; n < 8; ++n) {
                const float* kr = Kb + (n * 8 + g) * KSF + col;
                uint32_t kb0 = f2tf(kr[0]);
                uint32_t kb1 = f2tf(kr[4]);
                mma_tf32(sc[0][n], a0, kb0, kb1);
                mma_tf32(sc[1][n], a1, kb0, kb1);
            }
        }

        // ---- scale + mask + row maxima ----
        float tmax[4] = {-1e30f, -1e30f, -1e30f, -1e30f};
        #pragma unroll
        for (int gp = 0; gp < 2; ++gp) {
            #pragma unroll
            for (int n = 0; n < 8; ++n) {
                int col = t * NK + n * 8 + 2 * tg;
                uint2 m0 = *(const uint2*)(mr[2 * gp]     + col);
                uint2 m1 = *(const uint2*)(mr[2 * gp + 1] + col);
                float s0 = sc[gp][n][0] * SCALE; if (m0.x) s0 = -1e30f;
                float s1 = sc[gp][n][1] * SCALE; if (m0.y) s1 = -1e30f;
                float s2 = sc[gp][n][2] * SCALE; if (m1.x) s2 = -1e30f;
                float s3 = sc[gp][n][3] * SCALE; if (m1.y) s3 = -1e30f;
                sc[gp][n][0] = s0; sc[gp][n][1] = s1;
                sc[gp][n][2] = s2; sc[gp][n][3] = s3;
                tmax[2 * gp]     = fmaxf(tmax[2 * gp],     fmaxf(s0, s1));
                tmax[2 * gp + 1] = fmaxf(tmax[2 * gp + 1], fmaxf(s2, s3));
            }
        }
        #pragma unroll
        for (int j = 0; j < 4; ++j) {
            tmax[j] = fmaxf(tmax[j], __shfl_xor_sync(0xffffffffu, tmax[j], 1));
            tmax[j] = fmaxf(tmax[j], __shfl_xor_sync(0xffffffffu, tmax[j], 2));
        }

        float sf[4], corr[4];
        #pragma unroll
        for (int j = 0; j < 4; ++j) {
            float mn = fmaxf(mrw[j], tmax[j]);
            sf[j]   = (mn < -5e29f) ? 0.f : mn;
            corr[j] = __expf(mrw[j] - sf[j]);
            lrw[j] *= corr[j];
            mrw[j]  = mn;
        }
        #pragma unroll
        for (int gp = 0; gp < 2; ++gp)
            #pragma unroll
            for (int n = 0; n < 8; ++n) {
                ow[gp][n][0] *= corr[2 * gp];     ow[gp][n][1] *= corr[2 * gp];
                ow[gp][n][2] *= corr[2 * gp + 1]; ow[gp][n][3] *= corr[2 * gp + 1];
            }

        // ---- exp; P stays in C-fragment registers ----
        float ps[4] = {0.f, 0.f, 0.f, 0.f};
        #pragma unroll
        for (int gp = 0; gp < 2; ++gp) {
            #pragma unroll
            for (int n = 0; n < 8; ++n) {
                float p0 = __expf(sc[gp][n][0] - sf[2 * gp]);
                float p1 = __expf(sc[gp][n][1] - sf[2 * gp]);
                float p2 = __expf(sc[gp][n][2] - sf[2 * gp + 1]);
                float p3 = __expf(sc[gp][n][3] - sf[2 * gp + 1]);
                sc[gp][n][0] = p0; sc[gp][n][1] = p1;
                sc[gp][n][2] = p2; sc[gp][n][3] = p3;
                ps[2 * gp] += p0 + p1; ps[2 * gp + 1] += p2 + p3;
            }
        }
        #pragma unroll
        for (int j = 0; j < 4; ++j) {
            ps[j] += __shfl_xor_sync(0xffffffffu, ps[j], 1);
            ps[j] += __shfl_xor_sync(0xffffffffu, ps[j], 2);
            lrw[j] += ps[j];
        }

        // ---- PV: V rows pair-permuted so A-frag(P) == C-frag(sc): {c0,c2,c1,c3} ----
        #pragma unroll
        for (int ks = 0; ks < 8; ++ks) {
            uint32_t af0[4] = { f2tf(sc[0][ks][0]), f2tf(sc[0][ks][2]),
                                f2tf(sc[0][ks][1]), f2tf(sc[0][ks][3]) };
            uint32_t af1[4] = { f2tf(sc[1][ks][0]), f2tf(sc[1][ks][2]),
                                f2tf(sc[1][ks][1]), f2tf(sc[1][ks][3]) };
            #pragma unroll
            for (int n = 0; n < 8; ++n) {
                const float* vr = Vb + (ks * 8 + tg) * VSF + n * 8 + g;
                uint32_t vb0 = f2tf(vr[0]);
                uint32_t vb1 = f2tf(vr[4 * VSF]);
                mma_tf32(ow[0][n], af0, vb0, vb1);
                mma_tf32(ow[1][n], af1, vb0, vb1);
            }
        }

        __syncthreads();                       // everyone done reading buf bi
        if (t + 2 < NITER) prefetch(t + 2, bi);
        asm volatile("cp.async.commit_group;");  // dummy-safe: keeps group count in sync
    }

    // ---- epilogue ----
    float inv[4];
    #pragma unroll
    for (int j = 0; j < 4; ++j) inv[j] = (lrw[j] > 0.f) ? (1.f / lrw[j]) : 0.f;

    float* Ob = O + ((size_t)bh * Sq + (size_t)(qb * MQ + warp * 32)) * Dh;
    #pragma unroll
    for (int gp = 0; gp < 2; ++gp) {
        #pragma unroll
        for (int n = 0; n < 8; ++n) {
            int col = n * 8 + 2 * tg;
            *(float2*)&Ob[(g + 16 * gp) * Dh + col] =
                make_float2(ow[gp][n][0] * inv[2 * gp], ow[gp][n][1] * inv[2 * gp]);
            *(float2*)&Ob[(g + 16 * gp + 8) * Dh + col] =
                make_float2(ow[gp][n][2] * inv[2 * gp + 1], ow[gp][n][3] * inv[2 * gp + 1]);
        }
    }
}

extern "C" void kernel_launch(void* const* d_in, const int* in_sizes, int n_in,
                              void* d_out, int out_size)
{
    const float* Q = (const float*)d_in[0];
    const float* K = (const float*)d_in[1];
    const float* V = (const float*)d_in[2];
    const unsigned int* mask = (const unsigned int*)d_in[3];
    float* O = (float*)d_out;

    cudaFuncSetAttribute(sdpa_mma3, cudaFuncAttributeMaxDynamicSharedMemorySize, SMEM_BYTES);
    dim3 grid(2 * Hn * (Sq / MQ));   // 256
    sdpa_mma3<<<grid, THREADS, SMEM_BYTES>>>(Q, K, V, mask, O);
}

// round 6
// speedup vs baseline: 1.0709x; 1.0709x over previous
#include <cuda_runtime.h>
#include <cstdint>

// Problem shape
constexpr int Bv = 2, Hn = 16, Sq = 2048, Dh = 64;
constexpr float SCALE = 0.125f;

// Main-kernel tiling: CTA = 128 q-rows, 4 warps x 32 rows; 64-key tiles
constexpr int MQ = 128, NK = 64, THREADS = 128;
constexpr int NITER = Sq / NK;                 // 32

// smem (floats): stride 72 for Q/K/V tiles
constexpr int STR = 72;
constexpr int Q_OFF = 0;                        // 128 rows
constexpr int KBUF  = NK * STR * 4;             // 18432 B
constexpr int K_OFF = MQ * STR * 4;             // 36864
constexpr int V_OFF = K_OFF + 2 * KBUF;         // 73728
constexpr int SMEM_BYTES = V_OFF + 2 * KBUF;    // 110592

// Device scratch (static allocation is the sanctioned workaround)
__device__ uint32_t g_mb[Bv * Sq * 64];          // bit-packed mask, 1MB
__device__ uint32_t g_kt[32 * Sq * Dh];          // tf32 K, pair-permuted cols, 16.8MB
__device__ uint32_t g_vt[32 * Dh * Sq];          // tf32 V^T, 16.8MB

__device__ __forceinline__ uint32_t smem_u32(const void* p) {
    uint32_t a;
    asm("{ .reg .u64 t; cvta.to.shared.u64 t, %1; cvt.u32.u64 %0, t; }" : "=r"(a) : "l"(p));
    return a;
}
__device__ __forceinline__ uint32_t f2tf(float f) {
    uint32_t r;
    asm("cvt.rna.tf32.f32 %0, %1;" : "=r"(r) : "f"(f));
    return r;
}
__device__ __forceinline__ void cp16(uint32_t dst, const void* src) {
    asm volatile("cp.async.cg.shared.global [%0], [%1], 16;" :: "r"(dst), "l"(src));
}
__device__ __forceinline__ void mma_tf32(float* c, const uint32_t* a, uint32_t b0, uint32_t b1) {
    asm volatile(
        "mma.sync.aligned.m16n8k8.row.col.f32.tf32.tf32.f32 "
        "{%0,%1,%2,%3}, {%4,%5,%6,%7}, {%8,%9}, {%0,%1,%2,%3};"
        : "+f"(c[0]), "+f"(c[1]), "+f"(c[2]), "+f"(c[3])
        : "r"(a[0]), "r"(a[1]), "r"(a[2]), "r"(a[3]), "r"(b0), "r"(b1));
}

// ---------------- prepass: pack mask into bits ----------------
__global__ void pack_mask(const unsigned int* __restrict__ mask) {
    int idx = blockIdx.x * 256 + threadIdx.x;          // 0..262143
    const unsigned int* src = mask + (size_t)idx * 32;
    uint32_t bits = 0;
    #pragma unroll
    for (int j = 0; j < 32; ++j) bits |= (src[j] != 0u) << j;
    g_mb[idx] = bits;
}

// ---------------- prepass: tf32-round K with pair-permuted columns ----------------
// within each 8-col group: col j -> pos(j) = (j<4) ? 2j : 2(j-4)+1
__global__ void conv_k(const float* __restrict__ K) {
    int idx = blockIdx.x * 256 + threadIdx.x;          // 0..4194303
    int c = idx & 63, j = c & 7;
    int pos = (j < 4) ? 2 * j : 2 * (j - 4) + 1;
    g_kt[(idx & ~63) + (c & 56) + pos] = f2tf(K[idx]);
}

// ---------------- prepass: tf32-round + transpose V (V^T[d][s]) ----------------
__global__ void conv_v(const float* __restrict__ V) {
    __shared__ float sm[64][65];
    int bh = blockIdx.x >> 5;                          // 32 (b,h)
    int st = blockIdx.x & 31;                          // s-tile of 64
    int tid = threadIdx.x;
    int q = tid >> 6, l = tid & 63;                    // q=0..3, l=0..63
    const float* src = V + ((size_t)bh * Sq + (size_t)st * 64) * Dh;
    #pragma unroll
    for (int k = 0; k < 16; ++k) {
        int r = q * 16 + k;
        sm[r][l] = src[r * Dh + l];                    // coalesced over l
    }
    __syncthreads();
    uint32_t* dst = g_vt + (size_t)bh * Dh * Sq + (size_t)st * 64;
    #pragma unroll
    for (int k = 0; k < 16; ++k) {
        int d = q * 16 + k;
        dst[(size_t)d * Sq + l] = f2tf(sm[l][d]);      // coalesced over l
    }
}

// ---------------- main kernel ----------------
__global__ __launch_bounds__(THREADS)
void sdpa_mma4(const float* __restrict__ Q, float* __restrict__ O)
{
    extern __shared__ char smc[];
    const uint32_t sb = smem_u32(smc);
    float* Qs = (float*)smc;

    const int tid  = threadIdx.x;
    const int lane = tid & 31;
    const int warp = tid >> 5;
    const int g    = lane >> 2;
    const int tg   = lane & 3;

    const int nqb = Sq / MQ;                 // 16
    const int bh  = blockIdx.x / nqb;
    const int qb  = blockIdx.x % nqb;
    const int b   = bh / Hn;

    const uint32_t* Kg = g_kt + (size_t)bh * Sq * Dh;
    const uint32_t* Vg = g_vt + (size_t)bh * Dh * Sq;

    auto prefetch = [&](int t, int bi) {
        #pragma unroll
        for (int i = 0; i < 8; ++i) {
            int idx = tid + i * THREADS;     // 0..1023
            int r = idx >> 4, c = idx & 15;
            cp16(sb + K_OFF + bi * KBUF + r * (STR * 4) + c * 16,
                 Kg + (size_t)(t * NK + r) * Dh + c * 4);
            cp16(sb + V_OFF + bi * KBUF + r * (STR * 4) + c * 16,
                 Vg + (size_t)r * Sq + t * NK + c * 4);
        }
    };
    prefetch(0, 0); asm volatile("cp.async.commit_group;");
    prefetch(1, 1); asm volatile("cp.async.commit_group;");

    // ---- stage Q (tf32, pair-permuted cols) ----
    {
        const float4* qg = (const float4*)(Q + ((size_t)bh * Sq + (size_t)qb * MQ) * Dh);
        #pragma unroll
        for (int i = 0; i < 16; ++i) {
            int idx = tid + i * THREADS;     // 0..2047 float4s
            int r = idx >> 4, q4 = idx & 15;
            float4 v = qg[idx];
            int basep = (q4 & 1);
            uint32_t* dst = (uint32_t*)Qs + r * STR + (q4 >> 1) * 8 + basep;
            dst[0] = f2tf(v.x); dst[2] = f2tf(v.y);
            dst[4] = f2tf(v.z); dst[6] = f2tf(v.w);
        }
    }

    // packed mask row pointers: rows qbase + 8j
    const int qbase = qb * MQ + warp * 32 + g;
    const uint2* mpr[4];
    #pragma unroll
    for (int j = 0; j < 4; ++j)
        mpr[j] = (const uint2*)(g_mb + ((size_t)b * Sq + (size_t)(qbase + 8 * j)) * 64);

    float ow[2][8][4];
    #pragma unroll
    for (int gp = 0; gp < 2; ++gp)
        #pragma unroll
        for (int n = 0; n < 8; ++n)
            ow[gp][n][0] = ow[gp][n][1] = ow[gp][n][2] = ow[gp][n][3] = 0.f;
    float mrw[4] = {-1e30f, -1e30f, -1e30f, -1e30f};
    float lrw[4] = {0.f, 0.f, 0.f, 0.f};

    const float* Qw = Qs + (warp * 32) * STR;

    for (int t = 0; t < NITER; ++t) {
        const int bi = t & 1;
        uint2 mw[4];
        #pragma unroll
        for (int j = 0; j < 4; ++j) mw[j] = mpr[j][t];   // early, hidden under MMAs

        asm volatile("cp.async.wait_group 1;" ::: "memory");
        __syncthreads();

        const float* Kb = (const float*)(smc + K_OFF + bi * KBUF);
        const float* Vb = (const float*)(smc + V_OFF + bi * KBUF);

        // ---- QK^T ----
        float sc[2][8][4];
        #pragma unroll
        for (int gp = 0; gp < 2; ++gp)
            #pragma unroll
            for (int n = 0; n < 8; ++n)
                sc[gp][n][0] = sc[gp][n][1] = sc[gp][n][2] = sc[gp][n][3] = 0.f;

        #pragma unroll
        for (int ks = 0; ks < 8; ++ks) {
            const int c2 = ks * 8 + 2 * tg;
            float2 q0 = *(const float2*)(Qw + (g     ) * STR + c2);
            float2 q1 = *(const float2*)(Qw + (g +  8) * STR + c2);
            float2 q2 = *(const float2*)(Qw + (g + 16) * STR + c2);
            float2 q3 = *(const float2*)(Qw + (g + 24) * STR + c2);
            uint32_t a0[4] = { __float_as_uint(q0.x), __float_as_uint(q1.x),
                               __float_as_uint(q0.y), __float_as_uint(q1.y) };
            uint32_t a1[4] = { __float_as_uint(q2.x), __float_as_uint(q3.x),
                               __float_as_uint(q2.y), __float_as_uint(q3.y) };
            #pragma unroll
            for (int n = 0; n < 8; ++n) {
                float2 kb = *(const float2*)(Kb + (n * 8 + g) * STR + c2);
                uint32_t b0 = __float_as_uint(kb.x), b1 = __float_as_uint(kb.y);
                mma_tf32(sc[0][n], a0, b0, b1);
                mma_tf32(sc[1][n], a1, b0, b1);
            }
        }

        // ---- scale + mask (bit tests) + row maxima ----
        float tmax[4] = {-1e30f, -1e30f, -1e30f, -1e30f};
        #pragma unroll
        for (int gp = 0; gp < 2; ++gp) {
            #pragma unroll
            for (int n = 0; n < 8; ++n) {
                uint32_t w0 = (n < 4) ? mw[2 * gp].x     : mw[2 * gp].y;
                uint32_t w1 = (n < 4) ? mw[2 * gp + 1].x : mw[2 * gp + 1].y;
                int sh = ((n & 3) << 3) + 2 * tg;
                float s0 = sc[gp][n][0] * SCALE; if ((w0 >> sh) & 1)       s0 = -1e30f;
                float s1 = sc[gp][n][1] * SCALE; if ((w0 >> (sh + 1)) & 1) s1 = -1e30f;
                float s2 = sc[gp][n][2] * SCALE; if ((w1 >> sh) & 1)       s2 = -1e30f;
                float s3 = sc[gp][n][3] * SCALE; if ((w1 >> (sh + 1)) & 1) s3 = -1e30f;
                sc[gp][n][0] = s0; sc[gp][n][1] = s1;
                sc[gp][n][2] = s2; sc[gp][n][3] = s3;
                tmax[2 * gp]     = fmaxf(tmax[2 * gp],     fmaxf(s0, s1));
                tmax[2 * gp + 1] = fmaxf(tmax[2 * gp + 1], fmaxf(s2, s3));
            }
        }
        #pragma unroll
        for (int j = 0; j < 4; ++j) {
            tmax[j] = fmaxf(tmax[j], __shfl_xor_sync(0xffffffffu, tmax[j], 1));
            tmax[j] = fmaxf(tmax[j], __shfl_xor_sync(0xffffffffu, tmax[j], 2));
        }

        float sf[4], corr[4];
        #pragma unroll
        for (int j = 0; j < 4; ++j) {
            float mn = fmaxf(mrw[j], tmax[j]);
            sf[j]   = (mn < -5e29f) ? 0.f : mn;
            corr[j] = __expf(mrw[j] - sf[j]);
            lrw[j] *= corr[j];
            mrw[j]  = mn;
        }
        #pragma unroll
        for (int gp = 0; gp < 2; ++gp)
            #pragma unroll
            for (int n = 0; n < 8; ++n) {
                ow[gp][n][0] *= corr[2 * gp];     ow[gp][n][1] *= corr[2 * gp];
                ow[gp][n][2] *= corr[2 * gp + 1]; ow[gp][n][3] *= corr[2 * gp + 1];
            }

        // ---- exp; P stays in C-fragment registers ----
        float ps[4] = {0.f, 0.f, 0.f, 0.f};
        #pragma unroll
        for (int gp = 0; gp < 2; ++gp) {
            #pragma unroll
            for (int n = 0; n < 8; ++n) {
                float p0 = __expf(sc[gp][n][0] - sf[2 * gp]);
                float p1 = __expf(sc[gp][n][1] - sf[2 * gp]);
                float p2 = __expf(sc[gp][n][2] - sf[2 * gp + 1]);
                float p3 = __expf(sc[gp][n][3] - sf[2 * gp + 1]);
                sc[gp][n][0] = p0; sc[gp][n][1] = p1;
                sc[gp][n][2] = p2; sc[gp][n][3] = p3;
                ps[2 * gp] += p0 + p1; ps[2 * gp + 1] += p2 + p3;
            }
        }
        #pragma unroll
        for (int j = 0; j < 4; ++j) {
            ps[j] += __shfl_xor_sync(0xffffffffu, ps[j], 1);
            ps[j] += __shfl_xor_sync(0xffffffffu, ps[j], 2);
            lrw[j] += ps[j];
        }

        // ---- PV with V^T tiles; A-frag(P) == C-frag(sc) reorder {c0,c2,c1,c3} ----
        #pragma unroll
        for (int ks = 0; ks < 8; ++ks) {
            uint32_t af0[4] = { f2tf(sc[0][ks][0]), f2tf(sc[0][ks][2]),
                                f2tf(sc[0][ks][1]), f2tf(sc[0][ks][3]) };
            uint32_t af1[4] = { f2tf(sc[1][ks][0]), f2tf(sc[1][ks][2]),
                                f2tf(sc[1][ks][1]), f2tf(sc[1][ks][3]) };
            const int c2 = ks * 8 + 2 * tg;
            #pragma unroll
            for (int n = 0; n < 8; ++n) {
                float2 vb = *(const float2*)(Vb + (n * 8 + g) * STR + c2);
                uint32_t b0 = __float_as_uint(vb.x), b1 = __float_as_uint(vb.y);
                mma_tf32(ow[0][n], af0, b0, b1);
                mma_tf32(ow[1][n], af1, b0, b1);
            }
        }

        __syncthreads();
        if (t + 2 < NITER) prefetch(t + 2, bi);
        asm volatile("cp.async.commit_group;");
    }

    // ---- epilogue ----
    float inv[4];
    #pragma unroll
    for (int j = 0; j < 4; ++j) inv[j] = (lrw[j] > 0.f) ? (1.f / lrw[j]) : 0.f;

    float* Ob = O + ((size_t)bh * Sq + (size_t)(qb * MQ + warp * 32)) * Dh;
    #pragma unroll
    for (int gp = 0; gp < 2; ++gp) {
        #pragma unroll
        for (int n = 0; n < 8; ++n) {
            int col = n * 8 + 2 * tg;
            *(float2*)&Ob[(g + 16 * gp) * Dh + col] =
                make_float2(ow[gp][n][0] * inv[2 * gp], ow[gp][n][1] * inv[2 * gp]);
            *(float2*)&Ob[(g + 16 * gp + 8) * Dh + col] =
                make_float2(ow[gp][n][2] * inv[2 * gp + 1], ow[gp][n][3] * inv[2 * gp + 1]);
        }
    }
}

extern "C" void kernel_launch(void* const* d_in, const int* in_sizes, int n_in,
                              void* d_out, int out_size)
{
    const float* Q = (const float*)d_in[0];
    const float* K = (const float*)d_in[1];
    const float* V = (const float*)d_in[2];
    const unsigned int* mask = (const unsigned int*)d_in[3];
    float* O = (float*)d_out;

    pack_mask<<<Bv * Sq * 64 / 256, 256>>>(mask);
    conv_k<<<32 * Sq * Dh / 256, 256>>>(K);
    conv_v<<<32 * (Sq / 64), 256>>>(V);

    cudaFuncSetAttribute(sdpa_mma4, cudaFuncAttributeMaxDynamicSharedMemorySize, SMEM_BYTES);
    dim3 grid(2 * Hn * (Sq / MQ));   // 512
    sdpa_mma4<<<grid, THREADS, SMEM_BYTES>>>(Q, O);
}

// round 7
// speedup vs baseline: 1.7358x; 1.6210x over previous
#include <cuda_runtime.h>
#include <cuda_fp16.h>
#include <cstdint>

// Problem shape
constexpr int Bv = 2, Hn = 16, Sq = 2048, Dh = 64;

// Main-kernel tiling: CTA = 128 q-rows, 4 warps x 32 rows; 64-key tiles
constexpr int MQ = 128, NK = 64, THREADS = 128;
constexpr int NITER = Sq / NK;                 // 32

// smem: Q stage fp32 (stride 72 fl), K/V fp16 tiles (stride 72 halves)
constexpr int QSTR = 72;                        // floats
constexpr int STRH = 72;                        // halves
constexpr int Q_OFF = 0;                        // 128*72*4 = 36864 B
constexpr int KBUF  = NK * STRH * 2;            // 9216 B
constexpr int K_OFF = MQ * QSTR * 4;            // 36864
constexpr int V_OFF = K_OFF + 2 * KBUF;         // 55296
constexpr int SMEM_BYTES = V_OFF + 2 * KBUF;    // 73728

// Device scratch
__device__ uint32_t g_mb[Bv * Sq * 64];         // bit-packed mask, 1MB
__device__ __half  g_kh[32 * Sq * Dh];          // fp16 K row-major, 8.4MB
__device__ __half  g_vh[32 * Dh * Sq];          // fp16 V^T, 8.4MB

__device__ __forceinline__ uint32_t smem_u32(const void* p) {
    uint32_t a;
    asm("{ .reg .u64 t; cvta.to.shared.u64 t, %1; cvt.u32.u64 %0, t; }" : "=r"(a) : "l"(p));
    return a;
}
__device__ __forceinline__ void cp16(uint32_t dst, const void* src) {
    asm volatile("cp.async.cg.shared.global [%0], [%1], 16;" :: "r"(dst), "l"(src));
}
__device__ __forceinline__ uint32_t h2pack(float a, float b) {
    uint32_t r;
    asm("cvt.rn.f16x2.f32 %0, %2, %1;" : "=r"(r) : "f"(a), "f"(b));   // low=a, high=b
    return r;
}
__device__ __forceinline__ void mma_f16(float* c, const uint32_t* a, uint32_t b0, uint32_t b1) {
    asm volatile(
        "mma.sync.aligned.m16n8k16.row.col.f32.f16.f16.f32 "
        "{%0,%1,%2,%3}, {%4,%5,%6,%7}, {%8,%9}, {%0,%1,%2,%3};"
        : "+f"(c[0]), "+f"(c[1]), "+f"(c[2]), "+f"(c[3])
        : "r"(a[0]), "r"(a[1]), "r"(a[2]), "r"(a[3]), "r"(b0), "r"(b1));
}

// ---------------- prepass kernels ----------------
__global__ void pack_mask(const unsigned int* __restrict__ mask) {
    int idx = blockIdx.x * 256 + threadIdx.x;           // 0..8388607
    uint32_t bal = __ballot_sync(0xffffffffu, mask[idx] != 0u);
    if ((threadIdx.x & 31) == 0) g_mb[idx >> 5] = bal;
}
__global__ void conv_k(const float* __restrict__ K) {
    int idx = blockIdx.x * 256 + threadIdx.x;           // float4 units, 0..1048575
    float4 v = ((const float4*)K)[idx];
    ((uint2*)g_kh)[idx] = make_uint2(h2pack(v.x, v.y), h2pack(v.z, v.w));
}
__global__ void conv_v(const float* __restrict__ V) {
    __shared__ float sm[64][65];
    int bh = blockIdx.x >> 5;
    int st = blockIdx.x & 31;
    int tid = threadIdx.x;
    int q = tid >> 6, l = tid & 63;
    const float* src = V + ((size_t)bh * Sq + (size_t)st * 64) * Dh;
    #pragma unroll
    for (int k = 0; k < 16; ++k) {
        int r = q * 16 + k;
        sm[r][l] = src[r * Dh + l];
    }
    __syncthreads();
    __half* dst = g_vh + (size_t)bh * Dh * Sq + (size_t)st * 64;
    #pragma unroll
    for (int k = 0; k < 16; ++k) {
        int d = q * 16 + k;
        dst[(size_t)d * Sq + l] = __float2half_rn(sm[l][d]);
    }
}

// ---------------- main kernel ----------------
__global__ __launch_bounds__(THREADS)
void sdpa_h(const float* __restrict__ Q, float* __restrict__ O)
{
    extern __shared__ char smc[];
    const uint32_t sb = smem_u32(smc);
    float* Qs = (float*)smc;

    const int tid  = threadIdx.x;
    const int lane = tid & 31;
    const int warp = tid >> 5;
    const int g    = lane >> 2;
    const int tg   = lane & 3;

    const int nqb = Sq / MQ;                 // 16
    const int bh  = blockIdx.x / nqb;
    const int qb  = blockIdx.x % nqb;
    const int b   = bh / Hn;

    const __half* Kg = g_kh + (size_t)bh * Sq * Dh;
    const __half* Vg = g_vh + (size_t)bh * Dh * Sq;

    auto prefetch = [&](int t, int bi) {
        #pragma unroll
        for (int i = 0; i < 4; ++i) {
            int idx = tid + i * THREADS;     // 0..511
            int r = idx >> 3, c = idx & 7;   // row 0..63, 16B chunk 0..7
            cp16(sb + K_OFF + bi * KBUF + r * (STRH * 2) + c * 16,
                 Kg + (size_t)(t * NK + r) * Dh + c * 8);
            cp16(sb + V_OFF + bi * KBUF + r * (STRH * 2) + c * 16,
                 Vg + (size_t)r * Sq + t * NK + c * 8);
        }
    };
    prefetch(0, 0); asm volatile("cp.async.commit_group;");
    prefetch(1, 1); asm volatile("cp.async.commit_group;");

    // ---- stage this warp's 32 Q rows (fp32, pre-scaled by 1/8), warp-local ----
    float* Qw = Qs + (warp * 32) * QSTR;
    {
        const float4* qg = (const float4*)(Q + ((size_t)bh * Sq + (size_t)(qb * MQ + warp * 32)) * Dh);
        #pragma unroll
        for (int i = 0; i < 16; ++i) {
            int idx = lane + 32 * i;         // 0..511 float4s over 32 rows
            int r = idx >> 4, c4 = idx & 15;
            float4 v = qg[idx];
            float* dst = Qw + r * QSTR + c4 * 4;
            dst[0] = v.x * 0.125f; dst[1] = v.y * 0.125f;
            dst[2] = v.z * 0.125f; dst[3] = v.w * 0.125f;
        }
    }
    __syncwarp();

    // ---- build loop-invariant Q fragments (fp16), 32 regs ----
    uint32_t qf[2][4][4];
    #pragma unroll
    for (int gp = 0; gp < 2; ++gp) {
        #pragma unroll
        for (int ks = 0; ks < 4; ++ks) {
            int c0 = 16 * ks + 2 * tg;
            const float* r0 = Qw + (g + 16 * gp) * QSTR;
            const float* r1 = Qw + (g + 16 * gp + 8) * QSTR;
            qf[gp][ks][0] = h2pack(r0[c0],     r0[c0 + 1]);
            qf[gp][ks][1] = h2pack(r1[c0],     r1[c0 + 1]);
            qf[gp][ks][2] = h2pack(r0[c0 + 8], r0[c0 + 9]);
            qf[gp][ks][3] = h2pack(r1[c0 + 8], r1[c0 + 9]);
        }
    }

    // packed mask row pointers: rows qbase + 8j
    const int qbase = qb * MQ + warp * 32 + g;
    const uint2* mpr[4];
    #pragma unroll
    for (int j = 0; j < 4; ++j)
        mpr[j] = (const uint2*)(g_mb + ((size_t)b * Sq + (size_t)(qbase + 8 * j)) * 64);

    float ow[2][8][4];
    #pragma unroll
    for (int gp = 0; gp < 2; ++gp)
        #pragma unroll
        for (int n = 0; n < 8; ++n)
            ow[gp][n][0] = ow[gp][n][1] = ow[gp][n][2] = ow[gp][n][3] = 0.f;
    float mrw[4] = {-1e30f, -1e30f, -1e30f, -1e30f};
    float lrw[4] = {0.f, 0.f, 0.f, 0.f};

    for (int t = 0; t < NITER; ++t) {
        const int bi = t & 1;
        uint2 mw[4];
        #pragma unroll
        for (int j = 0; j < 4; ++j) mw[j] = mpr[j][t];

        asm volatile("cp.async.wait_group 1;" ::: "memory");
        __syncthreads();

        const __half* Kb = (const __half*)(smc + K_OFF + bi * KBUF);
        const __half* Vb = (const __half*)(smc + V_OFF + bi * KBUF);

        // ---- QK^T (scores pre-scaled via Q) ----
        float sc[2][8][4];
        #pragma unroll
        for (int gp = 0; gp < 2; ++gp)
            #pragma unroll
            for (int n = 0; n < 8; ++n)
                sc[gp][n][0] = sc[gp][n][1] = sc[gp][n][2] = sc[gp][n][3] = 0.f;

        #pragma unroll
        for (int ks = 0; ks < 4; ++ks) {
            const int c0 = 16 * ks + 2 * tg;
            #pragma unroll
            for (int n = 0; n < 8; ++n) {
                const __half* kr = Kb + (n * 8 + g) * STRH;
                uint32_t b0 = *(const uint32_t*)(kr + c0);
                uint32_t b1 = *(const uint32_t*)(kr + c0 + 8);
                mma_f16(sc[0][n], qf[0][ks], b0, b1);
                mma_f16(sc[1][n], qf[1][ks], b0, b1);
            }
        }

        // ---- mask (bit tests) + row maxima ----
        float tmax[4] = {-1e30f, -1e30f, -1e30f, -1e30f};
        #pragma unroll
        for (int gp = 0; gp < 2; ++gp) {
            #pragma unroll
            for (int n = 0; n < 8; ++n) {
                uint32_t w0 = (n < 4) ? mw[2 * gp].x     : mw[2 * gp].y;
                uint32_t w1 = (n < 4) ? mw[2 * gp + 1].x : mw[2 * gp + 1].y;
                int sh = ((n & 3) << 3) + 2 * tg;
                float s0 = sc[gp][n][0]; if ((w0 >> sh) & 1)       s0 = -1e30f;
                float s1 = sc[gp][n][1]; if ((w0 >> (sh + 1)) & 1) s1 = -1e30f;
                float s2 = sc[gp][n][2]; if ((w1 >> sh) & 1)       s2 = -1e30f;
                float s3 = sc[gp][n][3]; if ((w1 >> (sh + 1)) & 1) s3 = -1e30f;
                sc[gp][n][0] = s0; sc[gp][n][1] = s1;
                sc[gp][n][2] = s2; sc[gp][n][3] = s3;
                tmax[2 * gp]     = fmaxf(tmax[2 * gp],     fmaxf(s0, s1));
                tmax[2 * gp + 1] = fmaxf(tmax[2 * gp + 1], fmaxf(s2, s3));
            }
        }
        #pragma unroll
        for (int j = 0; j < 4; ++j) {
            tmax[j] = fmaxf(tmax[j], __shfl_xor_sync(0xffffffffu, tmax[j], 1));
            tmax[j] = fmaxf(tmax[j], __shfl_xor_sync(0xffffffffu, tmax[j], 2));
        }

        float sf[4], corr[4];
        #pragma unroll
        for (int j = 0; j < 4; ++j) {
            float mn = fmaxf(mrw[j], tmax[j]);
            sf[j]   = (mn < -5e29f) ? 0.f : mn;
            corr[j] = __expf(mrw[j] - sf[j]);
            lrw[j] *= corr[j];
            mrw[j]  = mn;
        }
        #pragma unroll
        for (int gp = 0; gp < 2; ++gp)
            #pragma unroll
            for (int n = 0; n < 8; ++n) {
                ow[gp][n][0] *= corr[2 * gp];     ow[gp][n][1] *= corr[2 * gp];
                ow[gp][n][2] *= corr[2 * gp + 1]; ow[gp][n][3] *= corr[2 * gp + 1];
            }

        // ---- exp ----
        float ps[4] = {0.f, 0.f, 0.f, 0.f};
        #pragma unroll
        for (int gp = 0; gp < 2; ++gp) {
            #pragma unroll
            for (int n = 0; n < 8; ++n) {
                float p0 = __expf(sc[gp][n][0] - sf[2 * gp]);
                float p1 = __expf(sc[gp][n][1] - sf[2 * gp]);
                float p2 = __expf(sc[gp][n][2] - sf[2 * gp + 1]);
                float p3 = __expf(sc[gp][n][3] - sf[2 * gp + 1]);
                sc[gp][n][0] = p0; sc[gp][n][1] = p1;
                sc[gp][n][2] = p2; sc[gp][n][3] = p3;
                ps[2 * gp] += p0 + p1; ps[2 * gp + 1] += p2 + p3;
            }
        }
        #pragma unroll
        for (int j = 0; j < 4; ++j) {
            ps[j] += __shfl_xor_sync(0xffffffffu, ps[j], 1);
            ps[j] += __shfl_xor_sync(0xffffffffu, ps[j], 2);
            lrw[j] += ps[j];
        }

        // ---- PV: A-frag = packed same-thread C-frags; B from V^T tile ----
        #pragma unroll
        for (int j = 0; j < 4; ++j) {
            uint32_t af0[4] = { h2pack(sc[0][2*j][0],   sc[0][2*j][1]),
                                h2pack(sc[0][2*j][2],   sc[0][2*j][3]),
                                h2pack(sc[0][2*j+1][0], sc[0][2*j+1][1]),
                                h2pack(sc[0][2*j+1][2], sc[0][2*j+1][3]) };
            uint32_t af1[4] = { h2pack(sc[1][2*j][0],   sc[1][2*j][1]),
                                h2pack(sc[1][2*j][2],   sc[1][2*j][3]),
                                h2pack(sc[1][2*j+1][0], sc[1][2*j+1][1]),
                                h2pack(sc[1][2*j+1][2], sc[1][2*j+1][3]) };
            const int c0 = 16 * j + 2 * tg;
            #pragma unroll
            for (int n = 0; n < 8; ++n) {
                const __half* vr = Vb + (n * 8 + g) * STRH;
                uint32_t b0 = *(const uint32_t*)(vr + c0);
                uint32_t b1 = *(const uint32_t*)(vr + c0 + 8);
                mma_f16(ow[0][n], af0, b0, b1);
                mma_f16(ow[1][n], af1, b0, b1);
            }
        }

        __syncthreads();
        if (t + 2 < NITER) prefetch(t + 2, bi);
        asm volatile("cp.async.commit_group;");
    }

    // ---- epilogue ----
    float inv[4];
    #pragma unroll
    for (int j = 0; j < 4; ++j) inv[j] = (lrw[j] > 0.f) ? (1.f / lrw[j]) : 0.f;

    float* Ob = O + ((size_t)bh * Sq + (size_t)(qb * MQ + warp * 32)) * Dh;
    #pragma unroll
    for (int gp = 0; gp < 2; ++gp) {
        #pragma unroll
        for (int n = 0; n < 8; ++n) {
            int col = n * 8 + 2 * tg;
            *(float2*)&Ob[(g + 16 * gp) * Dh + col] =
                make_float2(ow[gp][n][0] * inv[2 * gp], ow[gp][n][1] * inv[2 * gp]);
            *(float2*)&Ob[(g + 16 * gp + 8) * Dh + col] =
                make_float2(ow[gp][n][2] * inv[2 * gp + 1], ow[gp][n][3] * inv[2 * gp + 1]);
        }
    }
}

extern "C" void kernel_launch(void* const* d_in, const int* in_sizes, int n_in,
                              void* d_out, int out_size)
{
    const float* Q = (const float*)d_in[0];
    const float* K = (const float*)d_in[1];
    const float* V = (const float*)d_in[2];
    const unsigned int* mask = (const unsigned int*)d_in[3];
    float* O = (float*)d_out;

    pack_mask<<<Bv * Sq * Sq / 256, 256>>>(mask);
    conv_k<<<32 * Sq * Dh / 4 / 256, 256>>>(K);
    conv_v<<<32 * (Sq / 64), 256>>>(V);

    cudaFuncSetAttribute(sdpa_h, cudaFuncAttributeMaxDynamicSharedMemorySize, SMEM_BYTES);
    dim3 grid(2 * Hn * (Sq / MQ));   // 512
    sdpa_h<<<grid, THREADS, SMEM_BYTES>>>(Q, O);
}

// round 8
// speedup vs baseline: 2.1151x; 1.2185x over previous
#include <cuda_runtime.h>
#include <cuda_fp16.h>
#include <cstdint>

// Problem shape
constexpr int Bv = 2, Hn = 16, Sq = 2048, Dh = 64;

// Main-kernel tiling: CTA = 128 q-rows, 4 warps x 32 rows; 64-key tiles
constexpr int MQ = 128, NK = 64, THREADS = 128;
constexpr int NITER = Sq / NK;                 // 32

// smem: Q stage fp32 (stride 72 fl), K/V fp16 tiles (stride 72 halves)
constexpr int QSTR = 72;                        // floats
constexpr int STRH = 72;                        // halves
constexpr int KBUF  = NK * STRH * 2;            // 9216 B
constexpr int K_OFF = MQ * QSTR * 4;            // 36864
constexpr int V_OFF = K_OFF + 2 * KBUF;         // 55296
constexpr int SMEM_BYTES = V_OFF + 2 * KBUF;    // 73728

constexpr uint32_t ONESH2 = 0x3C003C00u;        // f16x2 {1.0, 1.0}

// Device scratch
__device__ uint32_t g_mb[Bv * Sq * 64];         // bit-packed mask, 1MB
__device__ __half  g_kh[32 * Sq * Dh];          // fp16 K row-major
__device__ __half  g_vh[32 * Dh * Sq];          // fp16 V^T

__device__ __forceinline__ uint32_t smem_u32(const void* p) {
    uint32_t a;
    asm("{ .reg .u64 t; cvta.to.shared.u64 t, %1; cvt.u32.u64 %0, t; }" : "=r"(a) : "l"(p));
    return a;
}
__device__ __forceinline__ void cp16(uint32_t dst, const void* src) {
    asm volatile("cp.async.cg.shared.global [%0], [%1], 16;" :: "r"(dst), "l"(src));
}
__device__ __forceinline__ uint32_t h2pack(float a, float b) {
    uint32_t r;
    asm("cvt.rn.f16x2.f32 %0, %2, %1;" : "=r"(r) : "f"(a), "f"(b));   // low=a, high=b
    return r;
}
__device__ __forceinline__ uint32_t ex2h2(uint32_t a) {
    uint32_t r;
    asm("ex2.approx.f16x2 %0, %1;" : "=r"(r) : "r"(a));
    return r;
}
__device__ __forceinline__ void mma_f16(float* c, const uint32_t* a, uint32_t b0, uint32_t b1) {
    asm volatile(
        "mma.sync.aligned.m16n8k16.row.col.f32.f16.f16.f32 "
        "{%0,%1,%2,%3}, {%4,%5,%6,%7}, {%8,%9}, {%0,%1,%2,%3};"
        : "+f"(c[0]), "+f"(c[1]), "+f"(c[2]), "+f"(c[3])
        : "r"(a[0]), "r"(a[1]), "r"(a[2]), "r"(a[3]), "r"(b0), "r"(b1));
}

// ---------------- prepass kernels ----------------
__global__ void pack_mask(const uint4* __restrict__ mask) {
    int w = blockIdx.x * 256 + threadIdx.x;             // word 0..262143
    const uint4* src = mask + (size_t)w * 8;            // 32 elems
    uint32_t bits = 0;
    #pragma unroll
    for (int j = 0; j < 8; ++j) {
        uint4 v = src[j];
        bits |= (uint32_t)(v.x != 0u) << (4 * j);
        bits |= (uint32_t)(v.y != 0u) << (4 * j + 1);
        bits |= (uint32_t)(v.z != 0u) << (4 * j + 2);
        bits |= (uint32_t)(v.w != 0u) << (4 * j + 3);
    }
    g_mb[w] = bits;
}
__global__ void conv_k(const float4* __restrict__ K) {
    int idx = blockIdx.x * 256 + threadIdx.x;           // 8-float unit
    float4 a = K[2 * idx], b = K[2 * idx + 1];
    ((uint4*)g_kh)[idx] = make_uint4(h2pack(a.x, a.y), h2pack(a.z, a.w),
                                     h2pack(b.x, b.y), h2pack(b.z, b.w));
}
__global__ void conv_v(const float* __restrict__ V) {
    __shared__ float sm[64][65];
    int bh = blockIdx.x >> 5;
    int st = blockIdx.x & 31;
    int tid = threadIdx.x;
    int q = tid >> 6, l = tid & 63;
    const float* src = V + ((size_t)bh * Sq + (size_t)st * 64) * Dh;
    #pragma unroll
    for (int k = 0; k < 16; ++k) {
        int r = q * 16 + k;
        sm[r][l] = src[r * Dh + l];
    }
    __syncthreads();
    __half* dst = g_vh + (size_t)bh * Dh * Sq + (size_t)st * 64;
    #pragma unroll
    for (int k = 0; k < 16; ++k) {
        int d = q * 16 + k;
        dst[(size_t)d * Sq + l] = __float2half_rn(sm[l][d]);
    }
}

// ---------------- main kernel ----------------
__global__ __launch_bounds__(THREADS)
void sdpa_h2(const float* __restrict__ Q, float* __restrict__ O)
{
    extern __shared__ char smc[];
    const uint32_t sb = smem_u32(smc);
    float* Qs = (float*)smc;

    const int tid  = threadIdx.x;
    const int lane = tid & 31;
    const int warp = tid >> 5;
    const int g    = lane >> 2;
    const int tg   = lane & 3;

    const int nqb = Sq / MQ;                 // 16
    const int bh  = blockIdx.x / nqb;
    const int qb  = blockIdx.x % nqb;
    const int b   = bh / Hn;

    const __half* Kg = g_kh + (size_t)bh * Sq * Dh;
    const __half* Vg = g_vh + (size_t)bh * Dh * Sq;

    auto prefetch = [&](int t, int bi) {
        #pragma unroll
        for (int i = 0; i < 4; ++i) {
            int idx = tid + i * THREADS;     // 0..511
            int r = idx >> 3, c = idx & 7;
            cp16(sb + K_OFF + bi * KBUF + r * (STRH * 2) + c * 16,
                 Kg + (size_t)(t * NK + r) * Dh + c * 8);
            cp16(sb + V_OFF + bi * KBUF + r * (STRH * 2) + c * 16,
                 Vg + (size_t)r * Sq + t * NK + c * 8);
        }
    };
    prefetch(0, 0); asm volatile("cp.async.commit_group;");
    prefetch(1, 1); asm volatile("cp.async.commit_group;");

    // ---- stage this warp's 32 Q rows (fp32, pre-scaled by log2e/8) ----
    constexpr float QSC = 0.125f * 1.4426950408889634f;
    float* Qw = Qs + (warp * 32) * QSTR;
    {
        const float4* qg = (const float4*)(Q + ((size_t)bh * Sq + (size_t)(qb * MQ + warp * 32)) * Dh);
        #pragma unroll
        for (int i = 0; i < 16; ++i) {
            int idx = lane + 32 * i;
            int r = idx >> 4, c4 = idx & 15;
            float4 v = qg[idx];
            float* dst = Qw + r * QSTR + c4 * 4;
            dst[0] = v.x * QSC; dst[1] = v.y * QSC;
            dst[2] = v.z * QSC; dst[3] = v.w * QSC;
        }
    }
    __syncwarp();

    // ---- loop-invariant Q fragments (fp16) ----
    uint32_t qf[2][4][4];
    #pragma unroll
    for (int gp = 0; gp < 2; ++gp) {
        #pragma unroll
        for (int ks = 0; ks < 4; ++ks) {
            int c0 = 16 * ks + 2 * tg;
            const float* r0 = Qw + (g + 16 * gp) * QSTR;
            const float* r1 = Qw + (g + 16 * gp + 8) * QSTR;
            qf[gp][ks][0] = h2pack(r0[c0],     r0[c0 + 1]);
            qf[gp][ks][1] = h2pack(r1[c0],     r1[c0 + 1]);
            qf[gp][ks][2] = h2pack(r0[c0 + 8], r0[c0 + 9]);
            qf[gp][ks][3] = h2pack(r1[c0 + 8], r1[c0 + 9]);
        }
    }

    const int qbase = qb * MQ + warp * 32 + g;
    const uint2* mpr[4];
    #pragma unroll
    for (int j = 0; j < 4; ++j)
        mpr[j] = (const uint2*)(g_mb + ((size_t)b * Sq + (size_t)(qbase + 8 * j)) * 64);

    float ow[2][8][4];
    float lacc[2][4];
    #pragma unroll
    for (int gp = 0; gp < 2; ++gp) {
        #pragma unroll
        for (int n = 0; n < 8; ++n)
            ow[gp][n][0] = ow[gp][n][1] = ow[gp][n][2] = ow[gp][n][3] = 0.f;
        lacc[gp][0] = lacc[gp][1] = lacc[gp][2] = lacc[gp][3] = 0.f;
    }
    float mrw[4] = {-1e30f, -1e30f, -1e30f, -1e30f};

    for (int t = 0; t < NITER; ++t) {
        const int bi = t & 1;
        uint2 mw[4];
        #pragma unroll
        for (int j = 0; j < 4; ++j) mw[j] = mpr[j][t];

        asm volatile("cp.async.wait_group 1;" ::: "memory");
        __syncthreads();

        const __half* Kb = (const __half*)(smc + K_OFF + bi * KBUF);
        const __half* Vb = (const __half*)(smc + V_OFF + bi * KBUF);

        // ---- QK^T (log2-domain scores, pre-scaled via Q) ----
        float sc[2][8][4];
        #pragma unroll
        for (int gp = 0; gp < 2; ++gp)
            #pragma unroll
            for (int n = 0; n < 8; ++n)
                sc[gp][n][0] = sc[gp][n][1] = sc[gp][n][2] = sc[gp][n][3] = 0.f;

        #pragma unroll
        for (int ks = 0; ks < 4; ++ks) {
            const int c0 = 16 * ks + 2 * tg;
            #pragma unroll
            for (int n = 0; n < 8; ++n) {
                const __half* kr = Kb + (n * 8 + g) * STRH;
                uint32_t b0 = *(const uint32_t*)(kr + c0);
                uint32_t b1 = *(const uint32_t*)(kr + c0 + 8);
                mma_f16(sc[0][n], qf[0][ks], b0, b1);
                mma_f16(sc[1][n], qf[1][ks], b0, b1);
            }
        }

        // ---- mask (bit tests) + row maxima ----
        float tmax[4] = {-1e30f, -1e30f, -1e30f, -1e30f};
        #pragma unroll
        for (int gp = 0; gp < 2; ++gp) {
            #pragma unroll
            for (int n = 0; n < 8; ++n) {
                uint32_t w0 = (n < 4) ? mw[2 * gp].x     : mw[2 * gp].y;
                uint32_t w1 = (n < 4) ? mw[2 * gp + 1].x : mw[2 * gp + 1].y;
                int sh = ((n & 3) << 3) + 2 * tg;
                float s0 = sc[gp][n][0]; if ((w0 >> sh) & 1)       s0 = -1e30f;
                float s1 = sc[gp][n][1]; if ((w0 >> (sh + 1)) & 1) s1 = -1e30f;
                float s2 = sc[gp][n][2]; if ((w1 >> sh) & 1)       s2 = -1e30f;
                float s3 = sc[gp][n][3]; if ((w1 >> (sh + 1)) & 1) s3 = -1e30f;
                sc[gp][n][0] = s0; sc[gp][n][1] = s1;
                sc[gp][n][2] = s2; sc[gp][n][3] = s3;
                tmax[2 * gp]     = fmaxf(tmax[2 * gp],     fmaxf(s0, s1));
                tmax[2 * gp + 1] = fmaxf(tmax[2 * gp + 1], fmaxf(s2, s3));
            }
        }
        #pragma unroll
        for (int j = 0; j < 4; ++j) {
            tmax[j] = fmaxf(tmax[j], __shfl_xor_sync(0xffffffffu, tmax[j], 1));
            tmax[j] = fmaxf(tmax[j], __shfl_xor_sync(0xffffffffu, tmax[j], 2));
        }

        float sf[4], corr[4];
        #pragma unroll
        for (int j = 0; j < 4; ++j) {
            float mn = fmaxf(mrw[j], tmax[j]);
            sf[j]   = (mn < -5e29f) ? 0.f : mn;
            corr[j] = exp2f(mrw[j] - sf[j]);     // log2 domain
            mrw[j]  = mn;
        }
        #pragma unroll
        for (int gp = 0; gp < 2; ++gp) {
            #pragma unroll
            for (int n = 0; n < 8; ++n) {
                ow[gp][n][0] *= corr[2 * gp];     ow[gp][n][1] *= corr[2 * gp];
                ow[gp][n][2] *= corr[2 * gp + 1]; ow[gp][n][3] *= corr[2 * gp + 1];
            }
            lacc[gp][0] *= corr[2 * gp];     lacc[gp][1] *= corr[2 * gp];
            lacc[gp][2] *= corr[2 * gp + 1]; lacc[gp][3] *= corr[2 * gp + 1];
        }

        // ---- exp2 in f16x2: result IS the PV A-fragment ----
        uint32_t pf[2][8][2];
        #pragma unroll
        for (int gp = 0; gp < 2; ++gp) {
            #pragma unroll
            for (int n = 0; n < 8; ++n) {
                uint32_t a01 = h2pack(sc[gp][n][0] - sf[2 * gp],
                                      sc[gp][n][1] - sf[2 * gp]);
                uint32_t a23 = h2pack(sc[gp][n][2] - sf[2 * gp + 1],
                                      sc[gp][n][3] - sf[2 * gp + 1]);
                pf[gp][n][0] = ex2h2(a01);
                pf[gp][n][1] = ex2h2(a23);
            }
        }

        // ---- PV + l (ones-column MMA) ----
        #pragma unroll
        for (int j = 0; j < 4; ++j) {
            uint32_t af0[4] = { pf[0][2*j][0], pf[0][2*j][1],
                                pf[0][2*j+1][0], pf[0][2*j+1][1] };
            uint32_t af1[4] = { pf[1][2*j][0], pf[1][2*j][1],
                                pf[1][2*j+1][0], pf[1][2*j+1][1] };
            const int c0 = 16 * j + 2 * tg;
            #pragma unroll
            for (int n = 0; n < 8; ++n) {
                const __half* vr = Vb + (n * 8 + g) * STRH;
                uint32_t b0 = *(const uint32_t*)(vr + c0);
                uint32_t b1 = *(const uint32_t*)(vr + c0 + 8);
                mma_f16(ow[0][n], af0, b0, b1);
                mma_f16(ow[1][n], af1, b0, b1);
            }
            mma_f16(lacc[0], af0, ONESH2, ONESH2);
            mma_f16(lacc[1], af1, ONESH2, ONESH2);
        }

        __syncthreads();
        if (t + 2 < NITER) prefetch(t + 2, bi);
        asm volatile("cp.async.commit_group;");
    }

    // ---- epilogue: l comes from the ones-column accumulator ----
    float inv[4];
    inv[0] = (lacc[0][0] > 0.f) ? (1.f / lacc[0][0]) : 0.f;
    inv[1] = (lacc[0][2] > 0.f) ? (1.f / lacc[0][2]) : 0.f;
    inv[2] = (lacc[1][0] > 0.f) ? (1.f / lacc[1][0]) : 0.f;
    inv[3] = (lacc[1][2] > 0.f) ? (1.f / lacc[1][2]) : 0.f;

    float* Ob = O + ((size_t)bh * Sq + (size_t)(qb * MQ + warp * 32)) * Dh;
    #pragma unroll
    for (int gp = 0; gp < 2; ++gp) {
        #pragma unroll
        for (int n = 0; n < 8; ++n) {
            int col = n * 8 + 2 * tg;
            *(float2*)&Ob[(g + 16 * gp) * Dh + col] =
                make_float2(ow[gp][n][0] * inv[2 * gp], ow[gp][n][1] * inv[2 * gp]);
            *(float2*)&Ob[(g + 16 * gp + 8) * Dh + col] =
                make_float2(ow[gp][n][2] * inv[2 * gp + 1], ow[gp][n][3] * inv[2 * gp + 1]);
        }
    }
}

extern "C" void kernel_launch(void* const* d_in, const int* in_sizes, int n_in,
                              void* d_out, int out_size)
{
    const float* Q = (const float*)d_in[0];
    const float* K = (const float*)d_in[1];
    const float* V = (const float*)d_in[2];
    const unsigned int* mask = (const unsigned int*)d_in[3];
    float* O = (float*)d_out;

    pack_mask<<<Bv * Sq * 64 / 256, 256>>>((const uint4*)mask);
    conv_k<<<32 * Sq * Dh / 8 / 256, 256>>>((const float4*)K);
    conv_v<<<32 * (Sq / 64), 256>>>(V);

    cudaFuncSetAttribute(sdpa_h2, cudaFuncAttributeMaxDynamicSharedMemorySize, SMEM_BYTES);
    dim3 grid(2 * Hn * (Sq / MQ));   // 512
    sdpa_h2<<<grid, THREADS, SMEM_BYTES>>>(Q, O);
}

// round 9
// speedup vs baseline: 2.3295x; 1.1014x over previous
#include <cuda_runtime.h>
#include <cuda_fp16.h>
#include <cstdint>

// Problem shape
constexpr int Bv = 2, Hn = 16, Sq = 2048, Dh = 64;

// Main-kernel tiling: CTA = 128 q-rows, 4 warps x 32 rows; 64-key tiles
constexpr int MQ = 128, NK = 64, THREADS = 128;
constexpr int NITER = Sq / NK;                 // 32

// smem: Q stage fp32 (stride 72 fl), K/V fp16 tiles (stride 72 halves)
constexpr int QSTR = 72;                        // floats
constexpr int STRH = 72;                        // halves
constexpr int KBUF  = NK * STRH * 2;            // 9216 B
constexpr int K_OFF = MQ * QSTR * 4;            // 36864
constexpr int V_OFF = K_OFF + 2 * KBUF;         // 55296
constexpr int SMEM_BYTES = V_OFF + 2 * KBUF;    // 73728

constexpr uint32_t ONESH2 = 0x3C003C00u;        // f16x2 {1.0, 1.0}

// Device scratch
__device__ uint32_t g_mb[Bv * Sq * 64];         // bit-packed mask, 1MB
__device__ __half  g_kh[32 * Sq * Dh];          // fp16 K row-major
__device__ __half  g_vh[32 * Dh * Sq];          // fp16 V^T

__device__ __forceinline__ uint32_t smem_u32(const void* p) {
    uint32_t a;
    asm("{ .reg .u64 t; cvta.to.shared.u64 t, %1; cvt.u32.u64 %0, t; }" : "=r"(a) : "l"(p));
    return a;
}
__device__ __forceinline__ void cp16(uint32_t dst, const void* src) {
    asm volatile("cp.async.cg.shared.global [%0], [%1], 16;" :: "r"(dst), "l"(src));
}
__device__ __forceinline__ uint32_t h2pack(float a, float b) {
    uint32_t r;
    asm("cvt.rn.f16x2.f32 %0, %2, %1;" : "=r"(r) : "f"(a), "f"(b));   // low=a, high=b
    return r;
}
__device__ __forceinline__ uint32_t ex2h2(uint32_t a) {
    uint32_t r;
    asm("ex2.approx.f16x2 %0, %1;" : "=r"(r) : "r"(a));
    return r;
}
__device__ __forceinline__ void mma_f16(float* c, const uint32_t* a, uint32_t b0, uint32_t b1) {
    asm volatile(
        "mma.sync.aligned.m16n8k16.row.col.f32.f16.f16.f32 "
        "{%0,%1,%2,%3}, {%4,%5,%6,%7}, {%8,%9}, {%0,%1,%2,%3};"
        : "+f"(c[0]), "+f"(c[1]), "+f"(c[2]), "+f"(c[3])
        : "r"(a[0]), "r"(a[1]), "r"(a[2]), "r"(a[3]), "r"(b0), "r"(b1));
}

// ---------------- prepass kernels ----------------
__global__ void pack_mask(const uint4* __restrict__ mask) {
    int w = blockIdx.x * 256 + threadIdx.x;             // word 0..262143
    const uint4* src = mask + (size_t)w * 8;            // 32 elems
    uint32_t bits = 0;
    #pragma unroll
    for (int j = 0; j < 8; ++j) {
        uint4 v = src[j];
        bits |= (uint32_t)(v.x != 0u) << (4 * j);
        bits |= (uint32_t)(v.y != 0u) << (4 * j + 1);
        bits |= (uint32_t)(v.z != 0u) << (4 * j + 2);
        bits |= (uint32_t)(v.w != 0u) << (4 * j + 3);
    }
    g_mb[w] = bits;
}
__global__ void conv_k(const float4* __restrict__ K) {
    int idx = blockIdx.x * 256 + threadIdx.x;           // 8-float unit
    float4 a = K[2 * idx], b = K[2 * idx + 1];
    ((uint4*)g_kh)[idx] = make_uint4(h2pack(a.x, a.y), h2pack(a.z, a.w),
                                     h2pack(b.x, b.y), h2pack(b.z, b.w));
}
__global__ void conv_v(const float* __restrict__ V) {
    __shared__ float sm[64][65];
    int bh = blockIdx.x >> 5;
    int st = blockIdx.x & 31;
    int tid = threadIdx.x;
    int q = tid >> 6, l = tid & 63;
    const float* src = V + ((size_t)bh * Sq + (size_t)st * 64) * Dh;
    #pragma unroll
    for (int k = 0; k < 16; ++k) {
        int r = q * 16 + k;
        sm[r][l] = src[r * Dh + l];
    }
    __syncthreads();
    __half* dst = g_vh + (size_t)bh * Dh * Sq + (size_t)st * 64;
    #pragma unroll
    for (int k = 0; k < 16; ++k) {
        int d = q * 16 + k;
        dst[(size_t)d * Sq + l] = __float2half_rn(sm[l][d]);
    }
}

// ---------------- main kernel ----------------
__global__ __launch_bounds__(THREADS)
void sdpa_h3(const float* __restrict__ Q, float* __restrict__ O)
{
    extern __shared__ char smc[];
    const uint32_t sb = smem_u32(smc);
    float* Qs = (float*)smc;

    const int tid  = threadIdx.x;
    const int lane = tid & 31;
    const int warp = tid >> 5;
    const int g    = lane >> 2;
    const int tg   = lane & 3;

    const int nqb = Sq / MQ;                 // 16
    const int bh  = blockIdx.x / nqb;
    const int qb  = blockIdx.x % nqb;
    const int b   = bh / Hn;

    const __half* Kg = g_kh + (size_t)bh * Sq * Dh;
    const __half* Vg = g_vh + (size_t)bh * Dh * Sq;

    auto prefetch = [&](int t, int bi) {
        #pragma unroll
        for (int i = 0; i < 4; ++i) {
            int idx = tid + i * THREADS;     // 0..511
            int r = idx >> 3, c = idx & 7;
            cp16(sb + K_OFF + bi * KBUF + r * (STRH * 2) + c * 16,
                 Kg + (size_t)(t * NK + r) * Dh + c * 8);
            cp16(sb + V_OFF + bi * KBUF + r * (STRH * 2) + c * 16,
                 Vg + (size_t)r * Sq + t * NK + c * 8);
        }
    };
    prefetch(0, 0); asm volatile("cp.async.commit_group;");
    prefetch(1, 1); asm volatile("cp.async.commit_group;");

    // ---- stage this warp's 32 Q rows (fp32, pre-scaled by log2e/8) ----
    constexpr float QSC = 0.125f * 1.4426950408889634f;
    float* Qw = Qs + (warp * 32) * QSTR;
    {
        const float4* qg = (const float4*)(Q + ((size_t)bh * Sq + (size_t)(qb * MQ + warp * 32)) * Dh);
        #pragma unroll
        for (int i = 0; i < 16; ++i) {
            int idx = lane + 32 * i;
            int r = idx >> 4, c4 = idx & 15;
            float4 v = qg[idx];
            float* dst = Qw + r * QSTR + c4 * 4;
            dst[0] = v.x * QSC; dst[1] = v.y * QSC;
            dst[2] = v.z * QSC; dst[3] = v.w * QSC;
        }
    }
    __syncwarp();

    // ---- loop-invariant Q fragments (fp16) ----
    uint32_t qf[2][4][4];
    #pragma unroll
    for (int gp = 0; gp < 2; ++gp) {
        #pragma unroll
        for (int ks = 0; ks < 4; ++ks) {
            int c0 = 16 * ks + 2 * tg;
            const float* r0 = Qw + (g + 16 * gp) * QSTR;
            const float* r1 = Qw + (g + 16 * gp + 8) * QSTR;
            qf[gp][ks][0] = h2pack(r0[c0],     r0[c0 + 1]);
            qf[gp][ks][1] = h2pack(r1[c0],     r1[c0 + 1]);
            qf[gp][ks][2] = h2pack(r0[c0 + 8], r0[c0 + 9]);
            qf[gp][ks][3] = h2pack(r1[c0 + 8], r1[c0 + 9]);
        }
    }

    const int qbase = qb * MQ + warp * 32 + g;
    const uint2* mpr[4];
    #pragma unroll
    for (int j = 0; j < 4; ++j)
        mpr[j] = (const uint2*)(g_mb + ((size_t)b * Sq + (size_t)(qbase + 8 * j)) * 64);

    float ow[2][8][4];
    float lacc[2][4];
    #pragma unroll
    for (int gp = 0; gp < 2; ++gp) {
        #pragma unroll
        for (int n = 0; n < 8; ++n)
            ow[gp][n][0] = ow[gp][n][1] = ow[gp][n][2] = ow[gp][n][3] = 0.f;
        lacc[gp][0] = lacc[gp][1] = lacc[gp][2] = lacc[gp][3] = 0.f;
    }

    const float NEGINF = __int_as_float(0xFF800000);

    for (int t = 0; t < NITER; ++t) {
        const int bi = t & 1;
        uint2 mw[4];
        #pragma unroll
        for (int j = 0; j < 4; ++j) mw[j] = mpr[j][t];

        asm volatile("cp.async.wait_group 1;" ::: "memory");
        __syncthreads();

        const __half* Kb = (const __half*)(smc + K_OFF + bi * KBUF);
        const __half* Vb = (const __half*)(smc + V_OFF + bi * KBUF);

        // ---- QK^T (log2-domain scores, pre-scaled via Q) ----
        float sc[2][8][4];
        #pragma unroll
        for (int gp = 0; gp < 2; ++gp)
            #pragma unroll
            for (int n = 0; n < 8; ++n)
                sc[gp][n][0] = sc[gp][n][1] = sc[gp][n][2] = sc[gp][n][3] = 0.f;

        #pragma unroll
        for (int ks = 0; ks < 4; ++ks) {
            const int c0 = 16 * ks + 2 * tg;
            #pragma unroll
            for (int n = 0; n < 8; ++n) {
                const __half* kr = Kb + (n * 8 + g) * STRH;
                uint32_t b0 = *(const uint32_t*)(kr + c0);
                uint32_t b1 = *(const uint32_t*)(kr + c0 + 8);
                mma_f16(sc[0][n], qf[0][ks], b0, b1);
                mma_f16(sc[1][n], qf[1][ks], b0, b1);
            }
        }

        // ---- mask (-> -inf) + exp2 in f16x2: result IS the PV A-fragment ----
        uint32_t pf[2][8][2];
        #pragma unroll
        for (int gp = 0; gp < 2; ++gp) {
            #pragma unroll
            for (int n = 0; n < 8; ++n) {
                uint32_t w0 = (n < 4) ? mw[2 * gp].x     : mw[2 * gp].y;
                uint32_t w1 = (n < 4) ? mw[2 * gp + 1].x : mw[2 * gp + 1].y;
                int sh = ((n & 3) << 3) + 2 * tg;
                float s0 = ((w0 >> sh) & 1)       ? NEGINF : sc[gp][n][0];
                float s1 = ((w0 >> (sh + 1)) & 1) ? NEGINF : sc[gp][n][1];
                float s2 = ((w1 >> sh) & 1)       ? NEGINF : sc[gp][n][2];
                float s3 = ((w1 >> (sh + 1)) & 1) ? NEGINF : sc[gp][n][3];
                pf[gp][n][0] = ex2h2(h2pack(s0, s1));
                pf[gp][n][1] = ex2h2(h2pack(s2, s3));
            }
        }

        // ---- PV + l (ones-column MMA) ----
        #pragma unroll
        for (int j = 0; j < 4; ++j) {
            uint32_t af0[4] = { pf[0][2*j][0], pf[0][2*j][1],
                                pf[0][2*j+1][0], pf[0][2*j+1][1] };
            uint32_t af1[4] = { pf[1][2*j][0], pf[1][2*j][1],
                                pf[1][2*j+1][0], pf[1][2*j+1][1] };
            const int c0 = 16 * j + 2 * tg;
            #pragma unroll
            for (int n = 0; n < 8; ++n) {
                const __half* vr = Vb + (n * 8 + g) * STRH;
                uint32_t b0 = *(const uint32_t*)(vr + c0);
                uint32_t b1 = *(const uint32_t*)(vr + c0 + 8);
                mma_f16(ow[0][n], af0, b0, b1);
                mma_f16(ow[1][n], af1, b0, b1);
            }
            mma_f16(lacc[0], af0, ONESH2, ONESH2);
            mma_f16(lacc[1], af1, ONESH2, ONESH2);
        }

        __syncthreads();
        if (t + 2 < NITER) prefetch(t + 2, bi);
        asm volatile("cp.async.commit_group;");
    }

    // ---- epilogue: l from the ones-column accumulator ----
    float inv[4];
    inv[0] = (lacc[0][0] > 0.f) ? (1.f / lacc[0][0]) : 0.f;
    inv[1] = (lacc[0][2] > 0.f) ? (1.f / lacc[0][2]) : 0.f;
    inv[2] = (lacc[1][0] > 0.f) ? (1.f / lacc[1][0]) : 0.f;
    inv[3] = (lacc[1][2] > 0.f) ? (1.f / lacc[1][2]) : 0.f;

    float* Ob = O + ((size_t)bh * Sq + (size_t)(qb * MQ + warp * 32)) * Dh;
    #pragma unroll
    for (int gp = 0; gp < 2; ++gp) {
        #pragma unroll
        for (int n = 0; n < 8; ++n) {
            int col = n * 8 + 2 * tg;
            *(float2*)&Ob[(g + 16 * gp) * Dh + col] =
                make_float2(ow[gp][n][0] * inv[2 * gp], ow[gp][n][1] * inv[2 * gp]);
            *(float2*)&Ob[(g + 16 * gp + 8) * Dh + col] =
                make_float2(ow[gp][n][2] * inv[2 * gp + 1], ow[gp][n][3] * inv[2 * gp + 1]);
        }
    }
}

extern "C" void kernel_launch(void* const* d_in, const int* in_sizes, int n_in,
                              void* d_out, int out_size)
{
    const float* Q = (const float*)d_in[0];
    const float* K = (const float*)d_in[1];
    const float* V = (const float*)d_in[2];
    const unsigned int* mask = (const unsigned int*)d_in[3];
    float* O = (float*)d_out;

    pack_mask<<<Bv * Sq * 64 / 256, 256>>>((const uint4*)mask);
    conv_k<<<32 * Sq * Dh / 8 / 256, 256>>>((const float4*)K);
    conv_v<<<32 * (Sq / 64), 256>>>(V);

    cudaFuncSetAttribute(sdpa_h3, cudaFuncAttributeMaxDynamicSharedMemorySize, SMEM_BYTES);
    dim3 grid(2 * Hn * (Sq / MQ));   // 512
    sdpa_h3<<<grid, THREADS, SMEM_BYTES>>>(Q, O);
}